// round 5
// baseline (speedup 1.0000x reference)
#include <cuda_runtime.h>
#include <math.h>
#include <stdint.h>

// ---------------- problem dims (fixed) ----------------
#define T_TOK  2048
#define HDIM   1024
#define IDIM   2816
#define NEXP   8
#define NASSIGN (T_TOK * 2)       // 4096 (token,expert) assignments

#define MAXT1  72                 // ceil(4096/64)  + 8 experts padding
#define MAXT2  40                 // ceil(4096/128) + 8

// ---------------- device scratch (static, allowed) ----------------
__device__ float g_act[(size_t)NASSIGN * IDIM];   // SwiGLU activations, 46 MB
__device__ int   g_perm_tok[NASSIGN];
__device__ float g_perm_w[NASSIGN];
__device__ int   g_tok_eid[NASSIGN];
__device__ float g_tok_w[NASSIGN];
__device__ int   g_counts[NEXP];
__device__ int   g_off[NEXP + 1];
__device__ int   g_cursor[NEXP];
__device__ int   g_t1_e[MAXT1], g_t1_r0[MAXT1];
__device__ int   g_t2_e[MAXT2], g_t2_r0[MAXT2];
__device__ int   g_n1, g_n2;

// ---------------- packed f32x2 helpers (sm_103a FFMA2) ----------------
__device__ __forceinline__ unsigned long long pk2(float lo, float hi) {
    unsigned long long r;
    asm("mov.b64 %0, {%1, %2};" : "=l"(r) : "f"(lo), "f"(hi));
    return r;
}
__device__ __forceinline__ void upk2(unsigned long long v, float& lo, float& hi) {
    asm("mov.b64 {%0, %1}, %2;" : "=f"(lo), "=f"(hi) : "l"(v));
}
__device__ __forceinline__ void ffma2(unsigned long long& acc,
                                      unsigned long long a,
                                      unsigned long long b) {
    asm("fma.rn.f32x2 %0, %1, %2, %0;" : "+l"(acc) : "l"(a), "l"(b));
}

// ---------------- kernel 0: reset counters ----------------
__global__ void k_init() {
    int i = threadIdx.x;
    if (i < NEXP) { g_counts[i] = 0; g_cursor[i] = 0; }
}

// ---------------- kernel 1: router (logits, top-2, renorm) ----------------
// one warp per token; 8 warps per block; grid = 256
__global__ void k_router(const float* __restrict__ x,
                         const float* __restrict__ gw,
                         float* __restrict__ out_logits,
                         int write_logits) {
    int warp = threadIdx.x >> 5, lane = threadIdx.x & 31;
    int t = blockIdx.x * 8 + warp;

    const float* xt = x + (size_t)t * HDIM;
    float xr[32];
#pragma unroll
    for (int i = 0; i < 32; i++) xr[i] = xt[i * 32 + lane];

    float lg[NEXP];
#pragma unroll
    for (int e = 0; e < NEXP; e++) {
        const float* ge = gw + e * HDIM;
        float s = 0.f;
#pragma unroll
        for (int i = 0; i < 32; i++) s += xr[i] * ge[i * 32 + lane];
#pragma unroll
        for (int o = 16; o > 0; o >>= 1) s += __shfl_xor_sync(0xffffffffu, s, o);
        lg[e] = s;
    }

    if (lane == 0) {
        if (write_logits) {
#pragma unroll
            for (int e = 0; e < NEXP; e++) out_logits[t * NEXP + e] = lg[e];
        }
        // top-2 (ties -> lowest index, matching lax.top_k)
        int a = 0;
#pragma unroll
        for (int e = 1; e < NEXP; e++) if (lg[e] > lg[a]) a = e;
        int b = (a == 0) ? 1 : 0;
#pragma unroll
        for (int e = 0; e < NEXP; e++) if (e != a && lg[e] > lg[b]) b = e;
        // renormalized softmax top-2 weights: pa/(pa+pb) = 1/(1+exp(lb-la))
        float wa = 1.f / (1.f + expf(lg[b] - lg[a]));
        g_tok_eid[2 * t]     = a; g_tok_w[2 * t]     = wa;
        g_tok_eid[2 * t + 1] = b; g_tok_w[2 * t + 1] = 1.f - wa;
        atomicAdd(&g_counts[a], 1);
        atomicAdd(&g_counts[b], 1);
    }
}

// ---------------- kernel 2: exclusive scan + tile tables ----------------
__global__ void k_scan() {
    if (threadIdx.x != 0) return;
    int off = 0;
    for (int e = 0; e < NEXP; e++) {
        g_off[e] = off; g_cursor[e] = off; off += g_counts[e];
    }
    g_off[NEXP] = off;
    int n1 = 0;
    for (int e = 0; e < NEXP; e++)
        for (int r = 0; r < g_counts[e]; r += 64) {
            g_t1_e[n1] = e; g_t1_r0[n1] = g_off[e] + r; n1++;
        }
    g_n1 = n1;
    int n2 = 0;
    for (int e = 0; e < NEXP; e++)
        for (int r = 0; r < g_counts[e]; r += 128) {
            g_t2_e[n2] = e; g_t2_r0[n2] = g_off[e] + r; n2++;
        }
    g_n2 = n2;
}

// ---------------- kernel 3: scatter assignments into expert segments ----------------
__global__ void k_scatter() {
    int t = blockIdx.x * blockDim.x + threadIdx.x;
    if (t >= T_TOK) return;
#pragma unroll
    for (int k = 0; k < 2; k++) {
        int e = g_tok_eid[2 * t + k];
        int pos = atomicAdd(&g_cursor[e], 1);
        g_perm_tok[pos] = t;
        g_perm_w[pos]   = g_tok_w[2 * t + k];
    }
}

// ---------------- kernel 4: grouped GEMM1 fused gate+up+SiLU ----------------
// C[64x64] per block, K = HDIM, dual B (w_gate, w_up); A rows gathered by token.
__global__ __launch_bounds__(256, 2)
void k_gemm1(const float* __restrict__ x,
             const float* __restrict__ wg,
             const float* __restrict__ wu) {
    int tt = blockIdx.x;
    if (tt >= g_n1) return;
    int e = g_t1_e[tt], row0 = g_t1_r0[tt], send = g_off[e + 1];
    int nblk = blockIdx.y * 64;

    __shared__ __align__(16) float As[16][64];
    __shared__ __align__(16) float Bg[16][64];
    __shared__ __align__(16) float Bu[16][64];

    int tid = threadIdx.x;
    int ar = tid >> 2, ac = (tid & 3) * 4;     // A tile loader: 64 rows x 16 k
    int br = tid >> 4, bc = (tid & 15) * 4;    // B tile loader: 16 k x 64 n
    int m0 = (tid >> 4) * 4, n0 = (tid & 15) * 4;

    int gr = row0 + ar;
    const float* arow = nullptr;
    if (gr < send) arow = x + (size_t)g_perm_tok[gr] * HDIM;
    const float* wge = wg + (size_t)e * HDIM * IDIM;
    const float* wue = wu + (size_t)e * HDIM * IDIM;

    unsigned long long accg[2][4], accu[2][4];
#pragma unroll
    for (int i = 0; i < 2; i++)
#pragma unroll
        for (int j = 0; j < 4; j++) { accg[i][j] = 0ull; accu[i][j] = 0ull; }

    for (int k0 = 0; k0 < HDIM; k0 += 16) {
        float4 av = make_float4(0.f, 0.f, 0.f, 0.f);
        if (arow) av = *(const float4*)(arow + k0 + ac);
        float4 bgv = *(const float4*)(wge + (size_t)(k0 + br) * IDIM + nblk + bc);
        float4 buv = *(const float4*)(wue + (size_t)(k0 + br) * IDIM + nblk + bc);
        __syncthreads();
        As[ac + 0][ar] = av.x; As[ac + 1][ar] = av.y;
        As[ac + 2][ar] = av.z; As[ac + 3][ar] = av.w;
        *(float4*)&Bg[br][bc] = bgv;
        *(float4*)&Bu[br][bc] = buv;
        __syncthreads();
#pragma unroll
        for (int kk = 0; kk < 16; kk++) {
            ulonglong2 a2 = *(const ulonglong2*)&As[kk][m0]; // (m0,m0+1),(m0+2,m0+3)
            float4 bg4 = *(const float4*)&Bg[kk][n0];
            float4 bu4 = *(const float4*)&Bu[kk][n0];
            unsigned long long bb;
            bb = pk2(bg4.x, bg4.x); ffma2(accg[0][0], a2.x, bb); ffma2(accg[1][0], a2.y, bb);
            bb = pk2(bg4.y, bg4.y); ffma2(accg[0][1], a2.x, bb); ffma2(accg[1][1], a2.y, bb);
            bb = pk2(bg4.z, bg4.z); ffma2(accg[0][2], a2.x, bb); ffma2(accg[1][2], a2.y, bb);
            bb = pk2(bg4.w, bg4.w); ffma2(accg[0][3], a2.x, bb); ffma2(accg[1][3], a2.y, bb);
            bb = pk2(bu4.x, bu4.x); ffma2(accu[0][0], a2.x, bb); ffma2(accu[1][0], a2.y, bb);
            bb = pk2(bu4.y, bu4.y); ffma2(accu[0][1], a2.x, bb); ffma2(accu[1][1], a2.y, bb);
            bb = pk2(bu4.z, bu4.z); ffma2(accu[0][2], a2.x, bb); ffma2(accu[1][2], a2.y, bb);
            bb = pk2(bu4.w, bu4.w); ffma2(accu[0][3], a2.x, bb); ffma2(accu[1][3], a2.y, bb);
        }
    }

    // epilogue: act = silu(g) * u
#pragma unroll
    for (int i2 = 0; i2 < 2; i2++) {
        float glo[4], ghi[4], ulo[4], uhi[4];
#pragma unroll
        for (int j = 0; j < 4; j++) {
            upk2(accg[i2][j], glo[j], ghi[j]);
            upk2(accu[i2][j], ulo[j], uhi[j]);
        }
        int rlo = row0 + m0 + 2 * i2;
        if (rlo < send) {
            float4 o;
            o.x = glo[0] * ulo[0] / (1.f + __expf(-glo[0]));
            o.y = glo[1] * ulo[1] / (1.f + __expf(-glo[1]));
            o.z = glo[2] * ulo[2] / (1.f + __expf(-glo[2]));
            o.w = glo[3] * ulo[3] / (1.f + __expf(-glo[3]));
            *(float4*)&g_act[(size_t)rlo * IDIM + nblk + n0] = o;
        }
        if (rlo + 1 < send) {
            float4 o;
            o.x = ghi[0] * uhi[0] / (1.f + __expf(-ghi[0]));
            o.y = ghi[1] * uhi[1] / (1.f + __expf(-ghi[1]));
            o.z = ghi[2] * uhi[2] / (1.f + __expf(-ghi[2]));
            o.w = ghi[3] * uhi[3] / (1.f + __expf(-ghi[3]));
            *(float4*)&g_act[(size_t)(rlo + 1) * IDIM + nblk + n0] = o;
        }
    }
}

// ---------------- kernel 5: grouped GEMM2 (down proj) + weighted scatter ----------------
// C[128x64] per block, K = IDIM; epilogue atomicAdd(w * y) into out.
__global__ __launch_bounds__(256, 2)
void k_gemm2(const float* __restrict__ wd, float* __restrict__ out) {
    int tt = blockIdx.x;
    if (tt >= g_n2) return;
    int e = g_t2_e[tt], row0 = g_t2_r0[tt], send = g_off[e + 1];
    int nblk = blockIdx.y * 64;

    __shared__ __align__(16) float As[16][128];
    __shared__ __align__(16) float Bs[16][64];

    int tid = threadIdx.x;
    int br = tid >> 4, bc = (tid & 15) * 4;
    int m0 = (tid >> 4) * 8, n0 = (tid & 15) * 4;

    int r0a = tid >> 2,        c0a = (tid & 3) * 4;       // rows 0..63
    int r1a = (tid >> 2) + 64, c1a = c0a;                 // rows 64..127

    const float* wde = wd + (size_t)e * IDIM * HDIM;

    unsigned long long acc[4][4];
#pragma unroll
    for (int i = 0; i < 4; i++)
#pragma unroll
        for (int j = 0; j < 4; j++) acc[i][j] = 0ull;

    for (int k0 = 0; k0 < IDIM; k0 += 16) {
        float4 a0 = make_float4(0.f, 0.f, 0.f, 0.f);
        float4 a1 = make_float4(0.f, 0.f, 0.f, 0.f);
        if (row0 + r0a < send)
            a0 = *(const float4*)&g_act[(size_t)(row0 + r0a) * IDIM + k0 + c0a];
        if (row0 + r1a < send)
            a1 = *(const float4*)&g_act[(size_t)(row0 + r1a) * IDIM + k0 + c1a];
        float4 bv = *(const float4*)(wde + (size_t)(k0 + br) * HDIM + nblk + bc);
        __syncthreads();
        As[c0a + 0][r0a] = a0.x; As[c0a + 1][r0a] = a0.y;
        As[c0a + 2][r0a] = a0.z; As[c0a + 3][r0a] = a0.w;
        As[c1a + 0][r1a] = a1.x; As[c1a + 1][r1a] = a1.y;
        As[c1a + 2][r1a] = a1.z; As[c1a + 3][r1a] = a1.w;
        *(float4*)&Bs[br][bc] = bv;
        __syncthreads();
#pragma unroll
        for (int kk = 0; kk < 16; kk++) {
            ulonglong2 av0 = *(const ulonglong2*)&As[kk][m0];
            ulonglong2 av1 = *(const ulonglong2*)&As[kk][m0 + 4];
            unsigned long long a2[4] = { av0.x, av0.y, av1.x, av1.y };
            float4 b4 = *(const float4*)&Bs[kk][n0];
            unsigned long long bb;
            bb = pk2(b4.x, b4.x);
            ffma2(acc[0][0], a2[0], bb); ffma2(acc[1][0], a2[1], bb);
            ffma2(acc[2][0], a2[2], bb); ffma2(acc[3][0], a2[3], bb);
            bb = pk2(b4.y, b4.y);
            ffma2(acc[0][1], a2[0], bb); ffma2(acc[1][1], a2[1], bb);
            ffma2(acc[2][1], a2[2], bb); ffma2(acc[3][1], a2[3], bb);
            bb = pk2(b4.z, b4.z);
            ffma2(acc[0][2], a2[0], bb); ffma2(acc[1][2], a2[1], bb);
            ffma2(acc[2][2], a2[2], bb); ffma2(acc[3][2], a2[3], bb);
            bb = pk2(b4.w, b4.w);
            ffma2(acc[0][3], a2[0], bb); ffma2(acc[1][3], a2[1], bb);
            ffma2(acc[2][3], a2[2], bb); ffma2(acc[3][3], a2[3], bb);
        }
    }

#pragma unroll
    for (int i2 = 0; i2 < 4; i2++) {
        float lo[4], hi[4];
#pragma unroll
        for (int j = 0; j < 4; j++) upk2(acc[i2][j], lo[j], hi[j]);
        int rlo = row0 + m0 + 2 * i2;
        if (rlo < send) {
            int tok = g_perm_tok[rlo];
            float w = g_perm_w[rlo];
            float* orow = out + (size_t)tok * HDIM + nblk + n0;
#pragma unroll
            for (int j = 0; j < 4; j++) atomicAdd(&orow[j], w * lo[j]);
        }
        if (rlo + 1 < send) {
            int tok = g_perm_tok[rlo + 1];
            float w = g_perm_w[rlo + 1];
            float* orow = out + (size_t)tok * HDIM + nblk + n0;
#pragma unroll
            for (int j = 0; j < 4; j++) atomicAdd(&orow[j], w * hi[j]);
        }
    }
}

// ---------------- launcher ----------------
extern "C" void kernel_launch(void* const* d_in, const int* in_sizes, int n_in,
                              void* d_out, int out_size) {
    (void)in_sizes; (void)n_in;
    const float* x  = (const float*)d_in[0];   // hidden_states [1,2048,1024]
    const float* gw = (const float*)d_in[1];   // gate_w [8,1024]
    const float* wg = (const float*)d_in[2];   // w_gate [8,1024,2816]
    const float* wu = (const float*)d_in[3];   // w_up   [8,1024,2816]
    const float* wd = (const float*)d_in[4];   // w_down [8,2816,1024]
    float* out = (float*)d_out;                // [out(T*H) | logits(T*E)]

    int write_logits = (out_size >= T_TOK * HDIM + T_TOK * NEXP) ? 1 : 0;

    cudaMemsetAsync(d_out, 0, (size_t)T_TOK * HDIM * sizeof(float));
    k_init<<<1, 32>>>();
    k_router<<<T_TOK / 8, 256>>>(x, gw, out + (size_t)T_TOK * HDIM, write_logits);
    k_scan<<<1, 1>>>();
    k_scatter<<<T_TOK / 256, 256>>>();
    k_gemm1<<<dim3(MAXT1, IDIM / 64), 256>>>(x, wg, wu);
    k_gemm2<<<dim3(MAXT2, HDIM / 64), 256>>>(wd, out);
}

// round 10
// speedup vs baseline: 1.7809x; 1.7809x over previous
#include <cuda_runtime.h>
#include <cuda_bf16.h>
#include <math.h>
#include <stdint.h>

// ---------------- problem dims (fixed) ----------------
#define T_TOK  2048
#define HDIM   1024
#define IDIM   2816
#define NEXP   8
#define NASSIGN 4096
#define NTMAX  80
#define APAD   (NASSIGN + 64)

#define WELEMS (NEXP * HDIM * IDIM)

// ---------------- device scratch (static globals, allowed) ----------------
__device__ __nv_bfloat16 g_xg_hi[APAD * HDIM];
__device__ __nv_bfloat16 g_xg_lo[APAD * HDIM];
__device__ __nv_bfloat16 g_act_hi[(size_t)APAD * IDIM];
__device__ __nv_bfloat16 g_act_lo[(size_t)APAD * IDIM];
__device__ float g_gbuf[(size_t)APAD * IDIM];     // X@Wg^T fp32
__device__ float g_ubuf[(size_t)APAD * IDIM];     // X@Wu^T fp32
__device__ float g_y[(size_t)APAD * HDIM];        // act@Wd^T fp32 (unweighted)
__device__ __nv_bfloat16 g_wgt_hi[WELEMS], g_wgt_lo[WELEMS];   // w_gate^T [E][I][H]
__device__ __nv_bfloat16 g_wut_hi[WELEMS], g_wut_lo[WELEMS];   // w_up^T   [E][I][H]
__device__ __nv_bfloat16 g_wdt_hi[WELEMS], g_wdt_lo[WELEMS];   // w_down^T [E][H][I]

__device__ int   g_perm_tok[NASSIGN];
__device__ float g_perm_w[NASSIGN];
__device__ int   g_pos[NASSIGN];
__device__ int   g_tok_eid[NASSIGN];
__device__ float g_tok_w[NASSIGN];
__device__ int   g_counts[NEXP];
__device__ int   g_off[NEXP + 1];
__device__ int   g_cursor[NEXP];
__device__ int   g_te[NTMAX], g_tr0[NTMAX];
__device__ int   g_nt;

// ---------------- PTX helpers (portable sm_80+ subset) ----------------
__device__ __forceinline__ uint32_t smem_u32(const void* p) {
    uint32_t a;
    asm("{ .reg .u64 t; cvta.to.shared.u64 t, %1; cvt.u32.u64 %0, t; }" : "=r"(a) : "l"(p));
    return a;
}
__device__ __forceinline__ void ldsm4(uint32_t* r, uint32_t a) {
    asm volatile("ldmatrix.sync.aligned.m8n8.x4.shared.b16 {%0,%1,%2,%3}, [%4];"
                 : "=r"(r[0]), "=r"(r[1]), "=r"(r[2]), "=r"(r[3]) : "r"(a));
}
__device__ __forceinline__ void mma16816(float* c, const uint32_t* a, uint32_t b0, uint32_t b1) {
    asm volatile(
        "mma.sync.aligned.m16n8k16.row.col.f32.bf16.bf16.f32 "
        "{%0,%1,%2,%3}, {%4,%5,%6,%7}, {%8,%9}, {%0,%1,%2,%3};"
        : "+f"(c[0]), "+f"(c[1]), "+f"(c[2]), "+f"(c[3])
        : "r"(a[0]), "r"(a[1]), "r"(a[2]), "r"(a[3]), "r"(b0), "r"(b1));
}
// 128B rows (KC=64 bf16), 8x16B chunks, XOR swizzle: conflict-free for ldmatrix
__device__ __forceinline__ uint32_t swz128(int row, int ch) {
    return (uint32_t)(row * 128 + (((ch ^ (row & 7)) & 7) << 4));
}

// ---------------- small kernels ----------------
__global__ void k_init() {
    int i = threadIdx.x;
    if (i < NEXP) { g_counts[i] = 0; g_cursor[i] = 0; }
}

__global__ void k_router(const float* __restrict__ x, const float* __restrict__ gw,
                         float* __restrict__ out_logits, int write_logits) {
    int warp = threadIdx.x >> 5, lane = threadIdx.x & 31;
    int t = blockIdx.x * 8 + warp;
    const float* xt = x + (size_t)t * HDIM;
    float xr[32];
#pragma unroll
    for (int i = 0; i < 32; i++) xr[i] = xt[i * 32 + lane];
    float lg[NEXP];
#pragma unroll
    for (int e = 0; e < NEXP; e++) {
        const float* ge = gw + e * HDIM;
        float s = 0.f;
#pragma unroll
        for (int i = 0; i < 32; i++) s += xr[i] * ge[i * 32 + lane];
#pragma unroll
        for (int o = 16; o > 0; o >>= 1) s += __shfl_xor_sync(0xffffffffu, s, o);
        lg[e] = s;
    }
    if (lane == 0) {
        if (write_logits) {
#pragma unroll
            for (int e = 0; e < NEXP; e++) out_logits[t * NEXP + e] = lg[e];
        }
        int a = 0;
#pragma unroll
        for (int e = 1; e < NEXP; e++) if (lg[e] > lg[a]) a = e;
        int b = (a == 0) ? 1 : 0;
#pragma unroll
        for (int e = 0; e < NEXP; e++) if (e != a && lg[e] > lg[b]) b = e;
        float wa = 1.f / (1.f + expf(lg[b] - lg[a]));
        g_tok_eid[2 * t]     = a; g_tok_w[2 * t]     = wa;
        g_tok_eid[2 * t + 1] = b; g_tok_w[2 * t + 1] = 1.f - wa;
        atomicAdd(&g_counts[a], 1);
        atomicAdd(&g_counts[b], 1);
    }
}

__global__ void k_scan() {
    if (threadIdx.x != 0) return;
    int off = 0;
    for (int e = 0; e < NEXP; e++) { g_off[e] = off; g_cursor[e] = off; off += g_counts[e]; }
    g_off[NEXP] = off;
    int nt = 0;
    for (int e = 0; e < NEXP; e++)
        for (int r = 0; r < g_counts[e]; r += 64) { g_te[nt] = e; g_tr0[nt] = g_off[e] + r; nt++; }
    g_nt = nt;
}

__global__ void k_scatter() {
    int t = blockIdx.x * blockDim.x + threadIdx.x;
    if (t >= T_TOK) return;
#pragma unroll
    for (int k = 0; k < 2; k++) {
        int e = g_tok_eid[2 * t + k];
        int pos = atomicAdd(&g_cursor[e], 1);
        g_perm_tok[pos] = t;
        g_perm_w[pos]   = g_tok_w[2 * t + k];
        g_pos[2 * t + k] = pos;
    }
}

__global__ void k_gather(const float* __restrict__ x) {
    int pos = blockIdx.x;
    int tok = g_perm_tok[pos];
    int i = threadIdx.x * 4;
    float4 v = *(const float4*)(x + (size_t)tok * HDIM + i);
    size_t o = (size_t)pos * HDIM + i;
    float vv[4] = { v.x, v.y, v.z, v.w };
#pragma unroll
    for (int j = 0; j < 4; j++) {
        __nv_bfloat16 h = __float2bfloat16(vv[j]);
        g_xg_hi[o + j] = h;
        g_xg_lo[o + j] = __float2bfloat16(vv[j] - __bfloat162float(h));
    }
}

// transpose W[e][K][N] fp32 -> hi/lo bf16 [e][N][K]. SEL picks DEVICE-GLOBAL output
// (device symbols referenced only in device code — never passed from host).
template<int SEL>
__global__ void k_transpose(const float* __restrict__ W) {
    constexpr int K = (SEL == 2) ? IDIM : HDIM;
    constexpr int N = (SEL == 2) ? HDIM : IDIM;
    __nv_bfloat16* hi = (SEL == 0) ? g_wgt_hi : (SEL == 1) ? g_wut_hi : g_wdt_hi;
    __nv_bfloat16* lo = (SEL == 0) ? g_wgt_lo : (SEL == 1) ? g_wut_lo : g_wdt_lo;

    __shared__ float tile[32][33];
    int e = blockIdx.z;
    const float* We = W + (size_t)e * K * N;
    size_t ob = (size_t)e * K * N;
    int n0 = blockIdx.x * 32, k0 = blockIdx.y * 32;
    int tx = threadIdx.x, ty = threadIdx.y;
#pragma unroll
    for (int i = 0; i < 4; i++)
        tile[ty * 4 + i][tx] = We[(size_t)(k0 + ty * 4 + i) * N + n0 + tx];
    __syncthreads();
#pragma unroll
    for (int i = 0; i < 4; i++) {
        int r = ty * 4 + i;
        float v = tile[tx][r];
        __nv_bfloat16 h = __float2bfloat16(v);
        size_t o = ob + (size_t)(n0 + r) * K + k0 + tx;
        hi[o] = h;
        lo[o] = __float2bfloat16(v - __bfloat162float(h));
    }
}

// ---------------- grouped GEMM: C[pos][Nd] = A[pos][Kd] @ B[e][Nd][Kd]^T ----------
// SEL=0: X@Wg->g_gbuf, SEL=1: X@Wu->g_ubuf, SEL=2: act@Wd->g_y.
// BM=64, BN=64, KC=64, single-buffered STATIC smem (32KB), 256 threads.
// 3-term bf16 split: AhBh + AlBh + AhBl, fp32 accumulate.
template<int SEL>
__global__ __launch_bounds__(256)
void k_gemm() {
    constexpr int Kd = (SEL == 2) ? IDIM : HDIM;
    constexpr int Nd = (SEL == 2) ? HDIM : IDIM;
    const __nv_bfloat16* Ah = (SEL == 2) ? g_act_hi : g_xg_hi;
    const __nv_bfloat16* Al = (SEL == 2) ? g_act_lo : g_xg_lo;
    const __nv_bfloat16* Bh = (SEL == 0) ? g_wgt_hi : (SEL == 1) ? g_wut_hi : g_wdt_hi;
    const __nv_bfloat16* Bl = (SEL == 0) ? g_wgt_lo : (SEL == 1) ? g_wut_lo : g_wdt_lo;
    float* C = (SEL == 0) ? g_gbuf : (SEL == 1) ? g_ubuf : g_y;

    __shared__ __align__(16) char sAh[8192];
    __shared__ __align__(16) char sAl[8192];
    __shared__ __align__(16) char sBh[8192];
    __shared__ __align__(16) char sBl[8192];

    int bx = blockIdx.x;
    if (bx >= g_nt) return;
    int e = g_te[bx], row0 = g_tr0[bx], send = g_off[e + 1];
    int nblk = blockIdx.y * 64;
    int tid = threadIdx.x, lane = tid & 31, warp = tid >> 5;
    int wm = (warp >> 1) * 16, wn = (warp & 1) * 32;   // 4M x 2N warps, 16x32 each

    const __nv_bfloat16* pa_h = Ah + (size_t)row0 * Kd;
    const __nv_bfloat16* pa_l = Al + (size_t)row0 * Kd;
    const __nv_bfloat16* pb_h = Bh + ((size_t)e * Nd + nblk) * Kd;
    const __nv_bfloat16* pb_l = Bl + ((size_t)e * Nd + nblk) * Kd;

    uint32_t uAh = smem_u32(sAh), uAl = smem_u32(sAl);
    uint32_t uBh = smem_u32(sBh), uBl = smem_u32(sBl);

    float acc[4][4];
#pragma unroll
    for (int j = 0; j < 4; j++)
#pragma unroll
        for (int k = 0; k < 4; k++) acc[j][k] = 0.f;

    int lrow = lane & 15, lch8 = lane >> 4;

    for (int c = 0; c < (Kd >> 6); c++) {
        int k0 = c << 6;
        __syncthreads();
#pragma unroll
        for (int r = 0; r < 2; r++) {
            int idx = r * 256 + tid, row = idx >> 3, ch = idx & 7;  // 64 rows x 8 chunks
            uint32_t sw = swz128(row, ch);
            size_t go = (size_t)row * Kd + k0 + ch * 8;
            *(uint4*)(sAh + sw) = *(const uint4*)(pa_h + go);
            *(uint4*)(sAl + sw) = *(const uint4*)(pa_l + go);
            *(uint4*)(sBh + sw) = *(const uint4*)(pb_h + go);
            *(uint4*)(sBl + sw) = *(const uint4*)(pb_l + go);
        }
        __syncthreads();
#pragma unroll
        for (int s = 0; s < 4; s++) {        // four k16 steps per 64-chunk
            int ch = 2 * s + lch8;
            uint32_t ah[4], al[4];
            {
                uint32_t sw = swz128(wm + lrow, ch);
                ldsm4(ah, uAh + sw);
                ldsm4(al, uAl + sw);
            }
#pragma unroll
            for (int p = 0; p < 2; p++) {
                uint32_t sw = swz128(wn + p * 16 + lrow, ch);
                uint32_t bh[4], bl[4];
                ldsm4(bh, uBh + sw);
                ldsm4(bl, uBl + sw);
                mma16816(acc[2 * p],     ah, bh[0], bh[2]);
                mma16816(acc[2 * p],     al, bh[0], bh[2]);
                mma16816(acc[2 * p],     ah, bl[0], bl[2]);
                mma16816(acc[2 * p + 1], ah, bh[1], bh[3]);
                mma16816(acc[2 * p + 1], al, bh[1], bh[3]);
                mma16816(acc[2 * p + 1], ah, bl[1], bl[3]);
            }
        }
    }

    // epilogue: raw fp32 store
    int r_off = lane >> 2, c_off = (lane & 3) * 2;
#pragma unroll
    for (int h = 0; h < 2; h++) {
        int row = row0 + wm + r_off + h * 8;
        if (row >= send) continue;
        float* crow = C + (size_t)row * Nd + nblk + wn + c_off;
#pragma unroll
        for (int nt = 0; nt < 4; nt++) {
            crow[nt * 8 + 0] = acc[nt][2 * h + 0];
            crow[nt * 8 + 1] = acc[nt][2 * h + 1];
        }
    }
}

// ---------------- SwiGLU elementwise: act = silu(g)*u -> hi/lo bf16 ----------------
__global__ void k_act() {
    int pos = blockIdx.x;
    size_t base = (size_t)pos * IDIM;
    for (int i = threadIdx.x; i < IDIM / 4; i += 256) {
        float4 g4 = *(const float4*)&g_gbuf[base + i * 4];
        float4 u4 = *(const float4*)&g_ubuf[base + i * 4];
        float gg[4] = { g4.x, g4.y, g4.z, g4.w };
        float uu[4] = { u4.x, u4.y, u4.z, u4.w };
#pragma unroll
        for (int j = 0; j < 4; j++) {
            float a = gg[j] * uu[j] / (1.f + __expf(-gg[j]));
            __nv_bfloat16 h = __float2bfloat16(a);
            g_act_hi[base + i * 4 + j] = h;
            g_act_lo[base + i * 4 + j] = __float2bfloat16(a - __bfloat162float(h));
        }
    }
}

// ---------------- combine: out[t] = w0*y[p0] + w1*y[p1] ----------------
__global__ void k_combine(float* __restrict__ out) {
    int t = blockIdx.x;
    int h = threadIdx.x * 4;
    int p0 = g_pos[2 * t], p1 = g_pos[2 * t + 1];
    float w0 = g_perm_w[p0], w1 = g_perm_w[p1];
    float4 a = *(const float4*)&g_y[(size_t)p0 * HDIM + h];
    float4 b = *(const float4*)&g_y[(size_t)p1 * HDIM + h];
    float4 o;
    o.x = w0 * a.x + w1 * b.x;
    o.y = w0 * a.y + w1 * b.y;
    o.z = w0 * a.z + w1 * b.z;
    o.w = w0 * a.w + w1 * b.w;
    *(float4*)(out + (size_t)t * HDIM + h) = o;
}

// ---------------- launcher (no device-global symbols passed as args!) ----------------
extern "C" void kernel_launch(void* const* d_in, const int* in_sizes, int n_in,
                              void* d_out, int out_size) {
    (void)in_sizes; (void)n_in;
    const float* x  = (const float*)d_in[0];
    const float* gw = (const float*)d_in[1];
    const float* wg = (const float*)d_in[2];
    const float* wu = (const float*)d_in[3];
    const float* wd = (const float*)d_in[4];
    float* out = (float*)d_out;

    int write_logits = (out_size >= T_TOK * HDIM + T_TOK * NEXP) ? 1 : 0;

    k_init<<<1, 32>>>();
    k_router<<<T_TOK / 8, 256>>>(x, gw, out + (size_t)T_TOK * HDIM, write_logits);
    k_scan<<<1, 1>>>();
    k_scatter<<<T_TOK / 256, 256>>>();
    k_gather<<<NASSIGN, 256>>>(x);
    // weight prep (hi/lo split + transpose to [E][N][K]); W in = harness pointers (valid)
    k_transpose<0><<<dim3(IDIM / 32, HDIM / 32, NEXP), dim3(32, 8)>>>(wg);
    k_transpose<1><<<dim3(IDIM / 32, HDIM / 32, NEXP), dim3(32, 8)>>>(wu);
    k_transpose<2><<<dim3(HDIM / 32, IDIM / 32, NEXP), dim3(32, 8)>>>(wd);
    // grouped GEMMs (static 32KB smem; globals referenced inside device code only)
    k_gemm<0><<<dim3(72, IDIM / 64), 256>>>();
    k_gemm<1><<<dim3(72, IDIM / 64), 256>>>();
    k_act<<<NASSIGN, 256>>>();
    k_gemm<2><<<dim3(72, HDIM / 64), 256>>>();
    k_combine<<<T_TOK, 256>>>(out);
}

// round 11
// speedup vs baseline: 1.9532x; 1.0967x over previous
#include <cuda_runtime.h>
#include <cuda_bf16.h>
#include <math.h>
#include <stdint.h>

// ---------------- problem dims (fixed) ----------------
#define T_TOK  2048
#define HDIM   1024
#define IDIM   2816
#define NEXP   8
#define NASSIGN 4096
#define NTMAX  48
#define APAD   (NASSIGN + 128)

#define WELEMS (NEXP * HDIM * IDIM)

// ---------------- device scratch (static globals, allowed) ----------------
__device__ __nv_bfloat16 g_xg_hi[APAD * HDIM];
__device__ __nv_bfloat16 g_xg_lo[APAD * HDIM];
__device__ __nv_bfloat16 g_act_hi[(size_t)APAD * IDIM];
__device__ __nv_bfloat16 g_act_lo[(size_t)APAD * IDIM];
__device__ float g_gbuf[(size_t)APAD * IDIM];     // X@Wg^T fp32
__device__ float g_ubuf[(size_t)APAD * IDIM];     // X@Wu^T fp32
__device__ float g_y[(size_t)APAD * HDIM];        // act@Wd^T fp32 (unweighted)
__device__ __nv_bfloat16 g_wgt_hi[WELEMS], g_wgt_lo[WELEMS];   // w_gate^T [E][I][H]
__device__ __nv_bfloat16 g_wut_hi[WELEMS], g_wut_lo[WELEMS];   // w_up^T   [E][I][H]
__device__ __nv_bfloat16 g_wdt_hi[WELEMS], g_wdt_lo[WELEMS];   // w_down^T [E][H][I]

__device__ int   g_perm_tok[NASSIGN];
__device__ float g_perm_w[NASSIGN];
__device__ int   g_pos[NASSIGN];
__device__ int   g_tok_eid[NASSIGN];
__device__ float g_tok_w[NASSIGN];
__device__ int   g_counts[NEXP];
__device__ int   g_off[NEXP + 1];
__device__ int   g_cursor[NEXP];
__device__ int   g_te[NTMAX], g_tr0[NTMAX];
__device__ int   g_nt;

// ---------------- PTX helpers (portable sm_80+ subset) ----------------
__device__ __forceinline__ uint32_t smem_u32(const void* p) {
    uint32_t a;
    asm("{ .reg .u64 t; cvta.to.shared.u64 t, %1; cvt.u32.u64 %0, t; }" : "=r"(a) : "l"(p));
    return a;
}
__device__ __forceinline__ void cpasync16(uint32_t dst, const void* src) {
    asm volatile("cp.async.cg.shared.global [%0], [%1], 16;" :: "r"(dst), "l"(src));
}
__device__ __forceinline__ void cp_commit() {
    asm volatile("cp.async.commit_group;" ::: "memory");
}
__device__ __forceinline__ void cp_wait1() {
    asm volatile("cp.async.wait_group 1;" ::: "memory");
}
__device__ __forceinline__ void ldsm4(uint32_t* r, uint32_t a) {
    asm volatile("ldmatrix.sync.aligned.m8n8.x4.shared.b16 {%0,%1,%2,%3}, [%4];"
                 : "=r"(r[0]), "=r"(r[1]), "=r"(r[2]), "=r"(r[3]) : "r"(a));
}
__device__ __forceinline__ void mma16816(float* c, const uint32_t* a, uint32_t b0, uint32_t b1) {
    asm volatile(
        "mma.sync.aligned.m16n8k16.row.col.f32.bf16.bf16.f32 "
        "{%0,%1,%2,%3}, {%4,%5,%6,%7}, {%8,%9}, {%0,%1,%2,%3};"
        : "+f"(c[0]), "+f"(c[1]), "+f"(c[2]), "+f"(c[3])
        : "r"(a[0]), "r"(a[1]), "r"(a[2]), "r"(a[3]), "r"(b0), "r"(b1));
}
// 64B rows (KC=32 bf16), 4x16B chunks, XOR swizzle ch ^= (row>>1)&3:
// per ldmatrix phase, 8 consecutive rows at fixed ch hit 8 distinct 16B slots.
__device__ __forceinline__ uint32_t swz64(int row, int ch) {
    return (uint32_t)(row * 64 + (((ch ^ ((row >> 1) & 3)) & 3) << 4));
}

// ---------------- small kernels ----------------
__global__ void k_init() {
    int i = threadIdx.x;
    if (i < NEXP) { g_counts[i] = 0; g_cursor[i] = 0; }
}

__global__ void k_router(const float* __restrict__ x, const float* __restrict__ gw,
                         float* __restrict__ out_logits, int write_logits) {
    int warp = threadIdx.x >> 5, lane = threadIdx.x & 31;
    int t = blockIdx.x * 8 + warp;
    const float* xt = x + (size_t)t * HDIM;
    float xr[32];
#pragma unroll
    for (int i = 0; i < 32; i++) xr[i] = xt[i * 32 + lane];
    float lg[NEXP];
#pragma unroll
    for (int e = 0; e < NEXP; e++) {
        const float* ge = gw + e * HDIM;
        float s = 0.f;
#pragma unroll
        for (int i = 0; i < 32; i++) s += xr[i] * ge[i * 32 + lane];
#pragma unroll
        for (int o = 16; o > 0; o >>= 1) s += __shfl_xor_sync(0xffffffffu, s, o);
        lg[e] = s;
    }
    if (lane == 0) {
        if (write_logits) {
#pragma unroll
            for (int e = 0; e < NEXP; e++) out_logits[t * NEXP + e] = lg[e];
        }
        int a = 0;
#pragma unroll
        for (int e = 1; e < NEXP; e++) if (lg[e] > lg[a]) a = e;
        int b = (a == 0) ? 1 : 0;
#pragma unroll
        for (int e = 0; e < NEXP; e++) if (e != a && lg[e] > lg[b]) b = e;
        float wa = 1.f / (1.f + expf(lg[b] - lg[a]));
        g_tok_eid[2 * t]     = a; g_tok_w[2 * t]     = wa;
        g_tok_eid[2 * t + 1] = b; g_tok_w[2 * t + 1] = 1.f - wa;
        atomicAdd(&g_counts[a], 1);
        atomicAdd(&g_counts[b], 1);
    }
}

__global__ void k_scan() {
    if (threadIdx.x != 0) return;
    int off = 0;
    for (int e = 0; e < NEXP; e++) { g_off[e] = off; g_cursor[e] = off; off += g_counts[e]; }
    g_off[NEXP] = off;
    int nt = 0;
    for (int e = 0; e < NEXP; e++)
        for (int r = 0; r < g_counts[e]; r += 128) { g_te[nt] = e; g_tr0[nt] = g_off[e] + r; nt++; }
    g_nt = nt;
}

__global__ void k_scatter() {
    int t = blockIdx.x * blockDim.x + threadIdx.x;
    if (t >= T_TOK) return;
#pragma unroll
    for (int k = 0; k < 2; k++) {
        int e = g_tok_eid[2 * t + k];
        int pos = atomicAdd(&g_cursor[e], 1);
        g_perm_tok[pos] = t;
        g_perm_w[pos]   = g_tok_w[2 * t + k];
        g_pos[2 * t + k] = pos;
    }
}

__global__ void k_gather(const float* __restrict__ x) {
    int pos = blockIdx.x;
    int tok = g_perm_tok[pos];
    int i = threadIdx.x * 4;
    float4 v = *(const float4*)(x + (size_t)tok * HDIM + i);
    size_t o = (size_t)pos * HDIM + i;
    float vv[4] = { v.x, v.y, v.z, v.w };
#pragma unroll
    for (int j = 0; j < 4; j++) {
        __nv_bfloat16 h = __float2bfloat16(vv[j]);
        g_xg_hi[o + j] = h;
        g_xg_lo[o + j] = __float2bfloat16(vv[j] - __bfloat162float(h));
    }
}

// transpose W[e][K][N] fp32 -> hi/lo bf16 [e][N][K] (globals only in device code)
template<int SEL>
__global__ void k_transpose(const float* __restrict__ W) {
    constexpr int K = (SEL == 2) ? IDIM : HDIM;
    constexpr int N = (SEL == 2) ? HDIM : IDIM;
    __nv_bfloat16* hi = (SEL == 0) ? g_wgt_hi : (SEL == 1) ? g_wut_hi : g_wdt_hi;
    __nv_bfloat16* lo = (SEL == 0) ? g_wgt_lo : (SEL == 1) ? g_wut_lo : g_wdt_lo;

    __shared__ float tile[32][33];
    int e = blockIdx.z;
    const float* We = W + (size_t)e * K * N;
    size_t ob = (size_t)e * K * N;
    int n0 = blockIdx.x * 32, k0 = blockIdx.y * 32;
    int tx = threadIdx.x, ty = threadIdx.y;
#pragma unroll
    for (int i = 0; i < 4; i++)
        tile[ty * 4 + i][tx] = We[(size_t)(k0 + ty * 4 + i) * N + n0 + tx];
    __syncthreads();
#pragma unroll
    for (int i = 0; i < 4; i++) {
        int r = ty * 4 + i;
        float v = tile[tx][r];
        __nv_bfloat16 h = __float2bfloat16(v);
        size_t o = ob + (size_t)(n0 + r) * K + k0 + tx;
        hi[o] = h;
        lo[o] = __float2bfloat16(v - __bfloat162float(h));
    }
}

// ---------------- grouped GEMM: C[pos][Nd] = A[pos][Kd] @ B[e][Nd][Kd]^T ----------
// SEL=0: X@Wg->g_gbuf, SEL=1: X@Wu->g_ubuf, SEL=2: act@Wd->g_y.
// BM=128, BN=64, KC=32, 2-stage cp.async double buffer, 48KB STATIC smem, 256 thr.
// 3-term bf16 split: AhBh + AlBh + AhBl, fp32 accumulate.

// per-stage offsets within 24KB: [Ah 8K | Al 8K | Bh 4K | Bl 4K]
#define ST_AH 0
#define ST_AL 8192
#define ST_BH 16384
#define ST_BL 20480
#define ST_SZ 24576

template<int SEL>
__global__ __launch_bounds__(256)
void k_gemm() {
    constexpr int Kd = (SEL == 2) ? IDIM : HDIM;
    constexpr int Nd = (SEL == 2) ? HDIM : IDIM;
    constexpr int NCH = Kd / 32;
    const __nv_bfloat16* Ah = (SEL == 2) ? g_act_hi : g_xg_hi;
    const __nv_bfloat16* Al = (SEL == 2) ? g_act_lo : g_xg_lo;
    const __nv_bfloat16* Bh = (SEL == 0) ? g_wgt_hi : (SEL == 1) ? g_wut_hi : g_wdt_hi;
    const __nv_bfloat16* Bl = (SEL == 0) ? g_wgt_lo : (SEL == 1) ? g_wut_lo : g_wdt_lo;
    float* C = (SEL == 0) ? g_gbuf : (SEL == 1) ? g_ubuf : g_y;

    __shared__ __align__(16) char smem[2 * ST_SZ];   // 48KB static

    int bx = blockIdx.x;
    if (bx >= g_nt) return;
    int e = g_te[bx], row0 = g_tr0[bx], send = g_off[e + 1];
    int nblk = blockIdx.y * 64;
    int tid = threadIdx.x, lane = tid & 31, warp = tid >> 5;
    int wm = (warp >> 1) * 32, wn = (warp & 1) * 32;   // 4M x 2N warps, 32x32 each

    const __nv_bfloat16* pa_h = Ah + (size_t)row0 * Kd;
    const __nv_bfloat16* pa_l = Al + (size_t)row0 * Kd;
    const __nv_bfloat16* pb_h = Bh + ((size_t)e * Nd + nblk) * Kd;
    const __nv_bfloat16* pb_l = Bl + ((size_t)e * Nd + nblk) * Kd;

    uint32_t sb = smem_u32(smem);

    // stage loader: A 128x32 (hi+lo), B 64x32 (hi+lo)
    auto issue = [&](int c) {
        if (c < NCH) {
            int k0 = c << 5;
            uint32_t b = sb + (uint32_t)(c & 1) * ST_SZ;
#pragma unroll
            for (int r = 0; r < 2; r++) {
                int idx = r * 256 + tid;           // 512 = 128 rows x 4 chunks
                int row = idx >> 2, ch = idx & 3;
                uint32_t sw = swz64(row, ch);
                size_t go = (size_t)row * Kd + k0 + ch * 8;
                cpasync16(b + ST_AH + sw, pa_h + go);
                cpasync16(b + ST_AL + sw, pa_l + go);
            }
            {
                int row = tid >> 2, ch = tid & 3;  // 256 = 64 rows x 4 chunks
                uint32_t sw = swz64(row, ch);
                size_t go = (size_t)row * Kd + k0 + ch * 8;
                cpasync16(b + ST_BH + sw, pb_h + go);
                cpasync16(b + ST_BL + sw, pb_l + go);
            }
        }
        cp_commit();
    };

    issue(0);
    issue(1);

    float acc[2][4][4];
#pragma unroll
    for (int i = 0; i < 2; i++)
#pragma unroll
        for (int j = 0; j < 4; j++)
#pragma unroll
            for (int k = 0; k < 4; k++) acc[i][j][k] = 0.f;

    int lrow = lane & 15, lch8 = lane >> 4;

    for (int c = 0; c < NCH; c++) {
        cp_wait1();
        __syncthreads();
        uint32_t base = sb + (uint32_t)(c & 1) * ST_SZ;
#pragma unroll
        for (int s = 0; s < 2; s++) {              // two k16 steps per 32-chunk
            int ch = 2 * s + lch8;
            uint32_t ah[2][4], al[2][4];
#pragma unroll
            for (int mt = 0; mt < 2; mt++) {
                uint32_t sw = swz64(wm + mt * 16 + lrow, ch);
                ldsm4(ah[mt], base + ST_AH + sw);
                ldsm4(al[mt], base + ST_AL + sw);
            }
#pragma unroll
            for (int p = 0; p < 2; p++) {
                uint32_t sw = swz64(wn + p * 16 + lrow, ch);
                uint32_t bh[4], bl[4];
                ldsm4(bh, base + ST_BH + sw);
                ldsm4(bl, base + ST_BL + sw);
#pragma unroll
                for (int mt = 0; mt < 2; mt++) {
                    mma16816(acc[mt][2 * p],     ah[mt], bh[0], bh[2]);
                    mma16816(acc[mt][2 * p],     al[mt], bh[0], bh[2]);
                    mma16816(acc[mt][2 * p],     ah[mt], bl[0], bl[2]);
                    mma16816(acc[mt][2 * p + 1], ah[mt], bh[1], bh[3]);
                    mma16816(acc[mt][2 * p + 1], al[mt], bh[1], bh[3]);
                    mma16816(acc[mt][2 * p + 1], ah[mt], bl[1], bl[3]);
                }
            }
        }
        __syncthreads();
        issue(c + 2);
    }

    // epilogue: raw fp32 store
    int r_off = lane >> 2, c_off = (lane & 3) * 2;
#pragma unroll
    for (int mt = 0; mt < 2; mt++) {
#pragma unroll
        for (int h = 0; h < 2; h++) {
            int row = row0 + wm + mt * 16 + r_off + h * 8;
            if (row >= send) continue;
            float* crow = C + (size_t)row * Nd + nblk + wn + c_off;
#pragma unroll
            for (int nt = 0; nt < 4; nt++) {
                crow[nt * 8 + 0] = acc[mt][nt][2 * h + 0];
                crow[nt * 8 + 1] = acc[mt][nt][2 * h + 1];
            }
        }
    }
}

// ---------------- SwiGLU elementwise: act = silu(g)*u -> hi/lo bf16 ----------------
__global__ void k_act() {
    int pos = blockIdx.x;
    size_t base = (size_t)pos * IDIM;
    for (int i = threadIdx.x; i < IDIM / 4; i += 256) {
        float4 g4 = *(const float4*)&g_gbuf[base + i * 4];
        float4 u4 = *(const float4*)&g_ubuf[base + i * 4];
        float gg[4] = { g4.x, g4.y, g4.z, g4.w };
        float uu[4] = { u4.x, u4.y, u4.z, u4.w };
#pragma unroll
        for (int j = 0; j < 4; j++) {
            float a = gg[j] * uu[j] / (1.f + __expf(-gg[j]));
            __nv_bfloat16 h = __float2bfloat16(a);
            g_act_hi[base + i * 4 + j] = h;
            g_act_lo[base + i * 4 + j] = __float2bfloat16(a - __bfloat162float(h));
        }
    }
}

// ---------------- combine: out[t] = w0*y[p0] + w1*y[p1] ----------------
__global__ void k_combine(float* __restrict__ out) {
    int t = blockIdx.x;
    int h = threadIdx.x * 4;
    int p0 = g_pos[2 * t], p1 = g_pos[2 * t + 1];
    float w0 = g_perm_w[p0], w1 = g_perm_w[p1];
    float4 a = *(const float4*)&g_y[(size_t)p0 * HDIM + h];
    float4 b = *(const float4*)&g_y[(size_t)p1 * HDIM + h];
    float4 o;
    o.x = w0 * a.x + w1 * b.x;
    o.y = w0 * a.y + w1 * b.y;
    o.z = w0 * a.z + w1 * b.z;
    o.w = w0 * a.w + w1 * b.w;
    *(float4*)(out + (size_t)t * HDIM + h) = o;
}

// ---------------- launcher (no device-global symbols passed as args) ----------------
extern "C" void kernel_launch(void* const* d_in, const int* in_sizes, int n_in,
                              void* d_out, int out_size) {
    (void)in_sizes; (void)n_in;
    const float* x  = (const float*)d_in[0];
    const float* gw = (const float*)d_in[1];
    const float* wg = (const float*)d_in[2];
    const float* wu = (const float*)d_in[3];
    const float* wd = (const float*)d_in[4];
    float* out = (float*)d_out;

    int write_logits = (out_size >= T_TOK * HDIM + T_TOK * NEXP) ? 1 : 0;

    k_init<<<1, 32>>>();
    k_router<<<T_TOK / 8, 256>>>(x, gw, out + (size_t)T_TOK * HDIM, write_logits);
    k_scan<<<1, 1>>>();
    k_scatter<<<T_TOK / 256, 256>>>();
    k_gather<<<NASSIGN, 256>>>(x);
    // weight prep (hi/lo split + transpose to [E][N][K])
    k_transpose<0><<<dim3(IDIM / 32, HDIM / 32, NEXP), dim3(32, 8)>>>(wg);
    k_transpose<1><<<dim3(IDIM / 32, HDIM / 32, NEXP), dim3(32, 8)>>>(wu);
    k_transpose<2><<<dim3(HDIM / 32, IDIM / 32, NEXP), dim3(32, 8)>>>(wd);
    // grouped GEMMs: BM=128, double-buffered cp.async, 48KB static smem
    k_gemm<0><<<dim3(40, IDIM / 64), 256>>>();
    k_gemm<1><<<dim3(40, IDIM / 64), 256>>>();
    k_act<<<NASSIGN, 256>>>();
    k_gemm<2><<<dim3(40, HDIM / 64), 256>>>();
    k_combine<<<T_TOK, 256>>>(out);
}